// round 9
// baseline (speedup 1.0000x reference)
#include <cuda_runtime.h>
#include <cstdint>
#include <math.h>

// NeuralField fused: persistent warp-specialized pipeline.
// 320 threads: warps 0-7 = GEMM (mma.sync TF32, 64x64 warp tiles, R6 layout),
// warps 8-9 = producers (final dot of tile t-1 during chunks 0-3, encode of
// tile t+1 during chunks 4-35). Weights stream as 16-row fragment-major chunks
// via cp.async double buffer. Each CTA loops over tiles (grid = #SMs).

#define NLEV    8
#define NPTS    262144
#define NTILES  2048
#define THREADS 320

#define HA_PITCH 72
#define HB_PITCH 264

#define B1_OFF   0                            // 128 x 264 activations
#define E_OFF    (128 * HB_PITCH)             // 33792: encode buffer 128 x 72
#define BS_OFF   (E_OFF + 128 * HA_PITCH)     // 43008
#define BS_F     4096                         // 16-row chunk, fragment-major (16KB)
#define W3_OFF   (BS_OFF + 2 * BS_F)          // 51200
#define SMEM_FLOATS (W3_OFF + 256)
#define SMEM_BYTES  (SMEM_FLOATS * 4)         // 205824

#define NCHUNK 36  // layer0: g 0..3 (K=64), layer1: 4..19, layer2: 20..35

struct LevelParams { float scale[NLEV]; int res[NLEV]; int size[NLEV]; };

// fragment-major weights: [36][nq(4)][kkI(2)][j(4)][lane(32)][e(4)]
__device__ float g_Wf[NCHUNK * BS_F];

// ------------------------------- helpers -----------------------------------
__device__ __forceinline__ uint32_t smem_u32(const void* p) {
    uint32_t a;
    asm("{ .reg .u64 t; cvta.to.shared.u64 t, %1; cvt.u32.u64 %0, t; }"
        : "=r"(a) : "l"(p));
    return a;
}
__device__ __forceinline__ uint32_t tf32r(float f) {
    uint32_t u;
    asm("cvt.rna.tf32.f32 %0, %1;" : "=r"(u) : "f"(f));
    return u;
}
__device__ __forceinline__ void cp_async16(uint32_t dst, const void* src) {
    asm volatile("cp.async.cg.shared.global [%0], [%1], 16;" :: "r"(dst), "l"(src));
}
#define CP_COMMIT() asm volatile("cp.async.commit_group;" ::: "memory")
#define CP_WAIT0()  asm volatile("cp.async.wait_group 0;" ::: "memory")

__device__ __forceinline__ void mma_tf32(float* d, const uint32_t* a,
                                         uint32_t b0, uint32_t b1) {
    asm volatile(
        "mma.sync.aligned.m16n8k8.row.col.f32.tf32.tf32.f32 "
        "{%0,%1,%2,%3}, {%4,%5,%6,%7}, {%8,%9}, {%0,%1,%2,%3};"
        : "+f"(d[0]), "+f"(d[1]), "+f"(d[2]), "+f"(d[3])
        : "r"(a[0]), "r"(a[1]), "r"(a[2]), "r"(a[3]), "r"(b0), "r"(b1));
}

// ---------------- prep: gather weights into fragment order + tf32 -----------
__global__ void wt_prep(const float* __restrict__ W0,
                        const float* __restrict__ W1,
                        const float* __restrict__ W2)
{
    const int idx = blockIdx.x * 256 + threadIdx.x;    // 0 .. 147455
    const int g    = idx >> 12;
    const int r    = idx & 4095;
    const int nq   = r >> 10;
    const int kkI  = (r >> 9) & 1;
    const int j    = (r >> 7) & 3;
    const int lane = (r >> 2) & 31;
    const int e    = r & 3;
    const int grp  = lane >> 2, tig = lane & 3;
    const int i16  = j * 4 + e;
    const int nt   = i16 >> 1;
    const int b    = i16 & 1;

    const float* W; int kc;
    if (g < 4)       { W = W0; kc = g * 16; }
    else if (g < 20) { W = W1; kc = (g - 4) * 16; }
    else             { W = W2; kc = (g - 20) * 16; }

    const int k = kc + kkI * 8 + 2 * tig + b;          // k-permuted slot
    const int n = nq * 64 + nt * 8 + grp;
    g_Wf[idx] = __uint_as_float(tf32r(W[k * 256 + n]));
}

// --------------------------------- device parts -----------------------------
__device__ __forceinline__ void prefetch_chunk(int c, uint32_t bs_base, int tid)
{
    const float* src = g_Wf + c * BS_F;
    const uint32_t dst = bs_base + (uint32_t)(c & 1) * (BS_F * 4);
    #pragma unroll
    for (int it = 0; it < 4; ++it) {
        const int i = tid + it * 256;                  // 0..1023 float4s
        cp_async16(dst + (uint32_t)i * 16, src + i * 4);
    }
    CP_COMMIT();
}

// producers (64 threads): encode 128 points (2/thread) into E
__device__ __forceinline__ void encode_tile(float* E, int base,
                                            const float* __restrict__ x,
                                            const float* __restrict__ table,
                                            const LevelParams& lp, int ptid)
{
    #pragma unroll
    for (int pp = 0; pp < 2; ++pp) {
        const int p  = ptid + pp * 64;
        const int gp = base + p;
        const float xx = x[2 * gp];
        const float yy = x[2 * gp + 1];

        #pragma unroll
        for (int l = 0; l < NLEV; ++l) {
            const float s  = lp.scale[l];
            const int res  = lp.res[l];
            const int size = lp.size[l];

            const float posx = xx * s + 0.5f;
            const float posy = yy * s + 0.5f;
            const float gx = floorf(posx), gy = floorf(posy);
            const float fx = posx - gx,    fy = posy - gy;
            const int   ix = (int)gx,      iy = (int)gy;
            const float wx = fx * fx * (3.0f - 2.0f * fx);
            const float wy = fy * fy * (3.0f - 2.0f * fy);

            float f[8];
            #pragma unroll
            for (int j = 0; j < 8; ++j) f[j] = 0.0f;

            #pragma unroll
            for (int dx = 0; dx < 2; ++dx) {
                const float wxx = dx ? wx : (1.0f - wx);
                #pragma unroll
                for (int dy = 0; dy < 2; ++dy) {
                    const float wyy = dy ? wy : (1.0f - wy);
                    int idx = (ix + dx) + (iy + dy) * res;   // < 2*size provably
                    if (idx >= size) idx -= size;
                    const float4* tp =
                        (const float4*)(table + ((size_t)(l * 8192 + idx) << 3));
                    const float w = wxx * wyy;
                    const float4 t0 = tp[0];
                    const float4 t1 = tp[1];
                    f[0] += w * t0.x; f[1] += w * t0.y;
                    f[2] += w * t0.z; f[3] += w * t0.w;
                    f[4] += w * t1.x; f[5] += w * t1.y;
                    f[6] += w * t1.z; f[7] += w * t1.w;
                }
            }
            float4 v0, v1;
            v0.x = __uint_as_float(tf32r(f[0])); v0.y = __uint_as_float(tf32r(f[1]));
            v0.z = __uint_as_float(tf32r(f[2])); v0.w = __uint_as_float(tf32r(f[3]));
            v1.x = __uint_as_float(tf32r(f[4])); v1.y = __uint_as_float(tf32r(f[5]));
            v1.z = __uint_as_float(tf32r(f[6])); v1.w = __uint_as_float(tf32r(f[7]));
            *(float4*)&E[p * HA_PITCH + l * 8]     = v0;
            *(float4*)&E[p * HA_PITCH + l * 8 + 4] = v1;
        }
    }
}

// producers (64 threads): out[r] = B1[r,:] . W3  (ReLU already applied)
__device__ __forceinline__ void dot_tile(const float* B1, const float* W3s,
                                         float* o, int ptid)
{
    #pragma unroll
    for (int rr = 0; rr < 2; ++rr) {
        const int r = ptid + rr * 64;
        const float* h = B1 + r * HB_PITCH;
        float s0 = 0.0f, s1 = 0.0f, s2 = 0.0f, s3 = 0.0f;
        #pragma unroll 8
        for (int k = 0; k < 256; k += 4) {
            s0 = fmaf(h[k],     W3s[k],     s0);
            s1 = fmaf(h[k + 1], W3s[k + 1], s1);
            s2 = fmaf(h[k + 2], W3s[k + 2], s2);
            s3 = fmaf(h[k + 3], W3s[k + 3], s3);
        }
        o[r] = (s0 + s1) + (s2 + s3);
    }
}

// --------------------------------- main kernel ------------------------------
__global__ __launch_bounds__(THREADS, 1)
void nf_main(const float* __restrict__ x, const float* __restrict__ table,
             const float* __restrict__ W3, float* __restrict__ out, LevelParams lp)
{
    extern __shared__ float smem[];
    float* B1  = smem + B1_OFF;
    float* E   = smem + E_OFF;
    float* W3s = smem + W3_OFF;
    const uint32_t bs_base = smem_u32(smem + BS_OFF);

    const int tid  = threadIdx.x;
    const bool consumer = tid < 256;
    const int wid  = tid >> 5;
    const int lane = tid & 31;
    const int grp  = lane >> 2;
    const int tig  = lane & 3;
    const int mb   = (wid & 1) * 64;
    const int nq   = wid >> 1;
    const int nb   = nq * 64;
    const int ptid = tid - 256;

    if (consumer) {
        prefetch_chunk(0, bs_base, tid);
        W3s[tid] = W3[tid];
    } else {
        encode_tile(E, blockIdx.x * 128, x, table, lp, ptid);   // tile 0 of this CTA
    }

    float acc[4][8][4];
    #pragma unroll
    for (int mt = 0; mt < 4; ++mt)
        #pragma unroll
        for (int nt = 0; nt < 8; ++nt)
            #pragma unroll
            for (int q = 0; q < 4; ++q) acc[mt][nt][q] = 0.0f;

    int prev_base = -1;
    for (int t = blockIdx.x; t < NTILES; t += gridDim.x) {
        for (int g = 0; g < NCHUNK; ++g) {
            CP_WAIT0();              // producers: no groups -> no-op
            __syncthreads();         // chunk g weights visible; prev buffer free

            if (consumer) {
                prefetch_chunk((g + 1) % NCHUNK, bs_base, tid);

                const int layer = (g < 4) ? 0 : ((g < 20) ? 1 : 2);
                const int kc0 =
                    16 * ((layer == 0) ? g : ((layer == 1) ? g - 4 : g - 20));
                const float* Ap = (layer == 0) ? E : B1;
                const int ap    = (layer == 0) ? HA_PITCH : HB_PITCH;
                const float* Bs = smem + BS_OFF + (g & 1) * BS_F;

                #pragma unroll
                for (int kkI = 0; kkI < 2; ++kkI) {
                    const int acol = kc0 + kkI * 8 + 2 * tig;
                    uint32_t a[4][4];
                    #pragma unroll
                    for (int mt = 0; mt < 4; ++mt) {
                        const int r0 = (mb + mt * 16 + grp) * ap + acol;
                        const float2 p0 = *(const float2*)&Ap[r0];
                        const float2 p1 = *(const float2*)&Ap[r0 + 8 * ap];
                        a[mt][0] = __float_as_uint(p0.x);
                        a[mt][1] = __float_as_uint(p1.x);
                        a[mt][2] = __float_as_uint(p0.y);
                        a[mt][3] = __float_as_uint(p1.y);
                    }
                    float bf[16];
                    #pragma unroll
                    for (int j = 0; j < 4; ++j)
                        *(float4*)&bf[j * 4] = *(const float4*)
                            &Bs[((nq * 2 + kkI) * 4 + j) * 128 + lane * 4];

                    #pragma unroll
                    for (int nt = 0; nt < 8; ++nt) {
                        const uint32_t b0 = __float_as_uint(bf[nt * 2]);
                        const uint32_t b1 = __float_as_uint(bf[nt * 2 + 1]);
                        #pragma unroll
                        for (int mt = 0; mt < 4; ++mt)
                            mma_tf32(acc[mt][nt], a[mt], b0, b1);
                    }
                }
            } else {
                if (g == 0) {
                    if (prev_base >= 0) dot_tile(B1, W3s, out + prev_base, ptid);
                } else if (g == 4) {
                    const int nt2 = t + gridDim.x;
                    if (nt2 < NTILES)
                        encode_tile(E, nt2 * 128, x, table, lp, ptid);
                }
            }

            if (g == 3 || g == 19 || g == 35) {
                __syncthreads();     // all B1/E reads + producer dot done
                if (consumer) {
                    const bool last = (g == 35);
                    #pragma unroll
                    for (int mt = 0; mt < 4; ++mt)
                        #pragma unroll
                        for (int nt = 0; nt < 8; ++nt) {
                            const int r0 = mb + mt * 16 + grp;
                            const int c0 = nb + nt * 8 + tig * 2;
                            float v0 = fmaxf(acc[mt][nt][0], 0.0f);
                            float v1 = fmaxf(acc[mt][nt][1], 0.0f);
                            float v2 = fmaxf(acc[mt][nt][2], 0.0f);
                            float v3 = fmaxf(acc[mt][nt][3], 0.0f);
                            if (!last) {
                                v0 = __uint_as_float(tf32r(v0));
                                v1 = __uint_as_float(tf32r(v1));
                                v2 = __uint_as_float(tf32r(v2));
                                v3 = __uint_as_float(tf32r(v3));
                            }
                            float2 w01; w01.x = v0; w01.y = v1;
                            float2 w23; w23.x = v2; w23.y = v3;
                            *(float2*)&B1[r0 * HB_PITCH + c0]       = w01;
                            *(float2*)&B1[(r0 + 8) * HB_PITCH + c0] = w23;
                            acc[mt][nt][0] = 0.0f; acc[mt][nt][1] = 0.0f;
                            acc[mt][nt][2] = 0.0f; acc[mt][nt][3] = 0.0f;
                        }
                }
            }
        }
        prev_base = t * 128;
    }

    __syncthreads();
    if (!consumer && prev_base >= 0)          // dot of this CTA's last tile
        dot_tile(B1, W3s, out + prev_base, ptid);
}

// --------------------------------- launcher ---------------------------------
extern "C" void kernel_launch(void* const* d_in, const int* in_sizes, int n_in,
                              void* d_out, int out_size)
{
    const float* x     = (const float*)d_in[0];
    const float* table = (const float*)d_in[1];
    const float* W0    = (const float*)d_in[2];
    const float* W1    = (const float*)d_in[3];
    const float* W2    = (const float*)d_in[4];
    const float* W3    = (const float*)d_in[5];
    float*       out   = (float*)d_out;

    LevelParams lp;
    for (int l = 0; l < NLEV; ++l) {
        double sc = 16.0 * pow(1.2599210739135742, (double)l) - 1.0;
        int res = (int)ceil(sc) + 1;
        long long sz = (long long)res * (long long)res;
        sz = ((sz + 7) / 8) * 8;
        if (sz > (1LL << 19)) sz = 1LL << 19;
        lp.scale[l] = (float)sc;
        lp.res[l]   = res;
        lp.size[l]  = (int)sz;
    }

    wt_prep<<<576, 256>>>(W0, W1, W2);

    int smCount = 148;
    cudaDeviceGetAttribute(&smCount, cudaDevAttrMultiProcessorCount, 0);
    int grid = smCount < NTILES ? smCount : NTILES;

    cudaFuncSetAttribute(nf_main, cudaFuncAttributeMaxDynamicSharedMemorySize,
                         SMEM_BYTES);
    nf_main<<<grid, THREADS, SMEM_BYTES>>>(x, table, W3, out, lp);
}

// round 10
// speedup vs baseline: 2.4049x; 2.4049x over previous
#include <cuda_runtime.h>
#include <cuda_fp16.h>
#include <cstdint>
#include <math.h>

// NeuralField fused: hashgrid encode + 3-layer MLP on mma.sync FP16 (fp32 acc)
// + final dot fused into the last epilogue.
// CTA = 128 points, 256 threads (8 warps), warp tile 64x64 (2 M x 4 N).
// Activations in half (k-permuted so A fragments are LDS.64); weights
// pre-gathered to per-thread fragment order (LDS.128), streamed via cp.async
// double buffer in 32-row (16KB) chunks.

#define NLEV    8
#define NPTS    262144
#define THREADS 256

#define EPW  40        // E pitch in half2 words (80 halves); 40 % 32 == 8
#define BPW  136       // B1 pitch in half2 words (272 halves); 136 % 32 == 8

#define B1_OFF   0
#define E_OFF    (128 * BPW * 4)             // 69632
#define BS_OFF   (E_OFF + 128 * EPW * 4)     // 90112
#define BS_B     16384                       // bytes per weight chunk
#define W3_OFF   (BS_OFF + 2 * BS_B)         // 122880
#define PART_OFF (W3_OFF + 1024)             // 123904
#define SMEM_BYTES (PART_OFF + 2048)         // 125952

#define NCHUNK 18  // layer0: g 0..1 (K=64), layer1: 2..9, layer2: 10..17

struct LevelParams { float scale[NLEV]; int res[NLEV]; int size[NLEV]; };

// fragment-major weights (half2 packed): [18][nq(4)][kkI(2)][j(4)][lane(32)][e(4)]
__device__ uint32_t g_Wf[NCHUNK * 4096];

// ------------------------------- helpers -----------------------------------
__device__ __forceinline__ uint32_t smem_u32(const void* p) {
    uint32_t a;
    asm("{ .reg .u64 t; cvta.to.shared.u64 t, %1; cvt.u32.u64 %0, t; }"
        : "=r"(a) : "l"(p));
    return a;
}
__device__ __forceinline__ void cp_async16(uint32_t dst, const void* src) {
    asm volatile("cp.async.cg.shared.global [%0], [%1], 16;" :: "r"(dst), "l"(src));
}
#define CP_COMMIT() asm volatile("cp.async.commit_group;" ::: "memory")
#define CP_WAIT0()  asm volatile("cp.async.wait_group 0;" ::: "memory")

__device__ __forceinline__ void mma_f16(float* d, uint32_t a0, uint32_t a1,
                                        uint32_t a2, uint32_t a3,
                                        uint32_t b0, uint32_t b1) {
    asm volatile(
        "mma.sync.aligned.m16n8k16.row.col.f32.f16.f16.f32 "
        "{%0,%1,%2,%3}, {%4,%5,%6,%7}, {%8,%9}, {%0,%1,%2,%3};"
        : "+f"(d[0]), "+f"(d[1]), "+f"(d[2]), "+f"(d[3])
        : "r"(a0), "r"(a1), "r"(a2), "r"(a3), "r"(b0), "r"(b1));
}

__device__ __forceinline__ uint32_t packh2(float lo, float hi) {
    __half2 h = __halves2half2(__float2half_rn(lo), __float2half_rn(hi));
    return *(uint32_t*)&h;
}

// ---------------- prep: gather weights into fragment order (half2) ----------
__global__ void wt_prep(const float* __restrict__ W0,
                        const float* __restrict__ W1,
                        const float* __restrict__ W2)
{
    const int idx = blockIdx.x * 256 + threadIdx.x;    // 0 .. 73727
    if (idx >= NCHUNK * 4096) return;
    const int g    = idx >> 12;
    const int r    = idx & 4095;
    const int nq   = r >> 10;
    const int kkI  = (r >> 9) & 1;
    const int j    = (r >> 7) & 3;
    const int lane = (r >> 2) & 31;
    const int e    = r & 3;
    const int grp  = lane >> 2, tig = lane & 3;
    const int i16  = j * 4 + e;
    const int nt   = i16 >> 1;
    const int b    = i16 & 1;

    const float* W; int kc;
    if (g < 2)       { W = W0; kc = g * 32; }
    else if (g < 10) { W = W1; kc = (g - 2) * 32; }
    else             { W = W2; kc = (g - 10) * 32; }

    const int k = kc + kkI * 16 + b * 8 + 2 * tig;     // b0: k=2t..; b1: k=8+2t..
    const int n = nq * 64 + nt * 8 + grp;
    g_Wf[idx] = packh2(W[k * 256 + n], W[(k + 1) * 256 + n]);
}

// --------------------------------- main kernel ------------------------------
__device__ __forceinline__ void prefetch_chunk(int g, uint32_t bs_base, int tid)
{
    const uint32_t* src = g_Wf + g * 4096;
    const uint32_t dst = bs_base + (uint32_t)(g & 1) * BS_B;
    #pragma unroll
    for (int it = 0; it < 4; ++it) {
        const int i = tid + it * 256;                  // 0..1023 float4s
        cp_async16(dst + (uint32_t)i * 16, src + i * 4);
    }
    CP_COMMIT();
}

__global__ __launch_bounds__(THREADS, 1)
void nf_main(const float* __restrict__ x, const float* __restrict__ table,
             const float* __restrict__ W3, float* __restrict__ out, LevelParams lp)
{
    extern __shared__ char smem[];
    uint32_t* B1w  = (uint32_t*)(smem + B1_OFF);   // half2 granularity
    uint32_t* Ew   = (uint32_t*)(smem + E_OFF);
    float*    W3s  = (float*)(smem + W3_OFF);
    float*    part = (float*)(smem + PART_OFF);
    const uint32_t bs_base = smem_u32(smem + BS_OFF);

    const int tid  = threadIdx.x;
    const int wid  = tid >> 5;
    const int lane = tid & 31;
    const int grp  = lane >> 2;
    const int tig  = lane & 3;
    const int mb   = (wid & 1) * 64;
    const int nq   = wid >> 1;
    const int nb   = nq * 64;

    prefetch_chunk(0, bs_base, tid);     // overlaps encode

    W3s[tid] = W3[tid];

    // ---------------- Encode: 2 threads/point, 4 levels/thread --------------
    // E stored k-permuted in half2: level l -> group g2=l>>1; pair j -> word
    // index g2*8 + 2j + (l&1).
    {
        const int p    = tid & 127;
        const int half = tid >> 7;
        const int gp   = blockIdx.x * 128 + p;
        const float xx = x[2 * gp];
        const float yy = x[2 * gp + 1];

        #pragma unroll
        for (int li = 0; li < 4; ++li) {
            const int l     = half * 4 + li;
            const float s   = lp.scale[l];
            const int res   = lp.res[l];
            const int size  = lp.size[l];

            const float posx = xx * s + 0.5f;
            const float posy = yy * s + 0.5f;
            const float gx = floorf(posx), gy = floorf(posy);
            const float fx = posx - gx,    fy = posy - gy;
            const int   ix = (int)gx,      iy = (int)gy;
            const float wx = fx * fx * (3.0f - 2.0f * fx);
            const float wy = fy * fy * (3.0f - 2.0f * fy);

            float f[8];
            #pragma unroll
            for (int j = 0; j < 8; ++j) f[j] = 0.0f;

            #pragma unroll
            for (int dx = 0; dx < 2; ++dx) {
                const float wxx = dx ? wx : (1.0f - wx);
                #pragma unroll
                for (int dy = 0; dy < 2; ++dy) {
                    const float wyy = dy ? wy : (1.0f - wy);
                    int idx = (ix + dx) + (iy + dy) * res;   // < 2*size (dense)
                    if (idx >= size) idx -= size;
                    const float4* tp =
                        (const float4*)(table + ((size_t)(l * 8192 + idx) << 3));
                    const float w = wxx * wyy;
                    const float4 t0 = tp[0];
                    const float4 t1 = tp[1];
                    f[0] += w * t0.x; f[1] += w * t0.y;
                    f[2] += w * t0.z; f[3] += w * t0.w;
                    f[4] += w * t1.x; f[5] += w * t1.y;
                    f[6] += w * t1.z; f[7] += w * t1.w;
                }
            }
            const int base = p * EPW + (l >> 1) * 8 + (l & 1);
            #pragma unroll
            for (int j = 0; j < 4; ++j)
                Ew[base + 2 * j] = packh2(f[2 * j], f[2 * j + 1]);
        }
    }

    // ---------------- 18 chunks across 3 layers ------------------------------
    float acc[4][8][4];
    #pragma unroll
    for (int mt = 0; mt < 4; ++mt)
        #pragma unroll
        for (int nt = 0; nt < 8; ++nt)
            #pragma unroll
            for (int q = 0; q < 4; ++q) acc[mt][nt][q] = 0.0f;

    for (int g = 0; g < NCHUNK; ++g) {
        CP_WAIT0();
        __syncthreads();
        if (g + 1 < NCHUNK) prefetch_chunk(g + 1, bs_base, tid);

        const int layer = (g < 2) ? 0 : ((g < 10) ? 1 : 2);
        const int gch   = (layer == 0) ? g : ((layer == 1) ? g - 2 : g - 10);
        const uint32_t* Aw = (layer == 0) ? Ew : B1w;
        const int apw      = (layer == 0) ? EPW : BPW;
        const uint32_t* Bs = (const uint32_t*)(smem + BS_OFF + (g & 1) * BS_B);

        #pragma unroll
        for (int kkI = 0; kkI < 2; ++kkI) {
            const int goff = (gch * 2 + kkI) * 8 + 2 * tig;  // k16-group base word
            uint32_t a[4][4];
            #pragma unroll
            for (int mt = 0; mt < 4; ++mt) {
                const int r0 = (mb + mt * 16 + grp) * apw + goff;
                const uint2 u0 = *(const uint2*)&Aw[r0];            // a0, a2
                const uint2 u1 = *(const uint2*)&Aw[r0 + 8 * apw];  // a1, a3
                a[mt][0] = u0.x; a[mt][1] = u1.x;
                a[mt][2] = u0.y; a[mt][3] = u1.y;
            }
            float bf[16];
            #pragma unroll
            for (int j = 0; j < 4; ++j)
                *(float4*)&bf[j * 4] = *(const float4*)
                    &Bs[((nq * 2 + kkI) * 4 + j) * 128 + lane * 4];

            #pragma unroll
            for (int nt = 0; nt < 8; ++nt) {
                const uint32_t b0 = __float_as_uint(bf[nt * 2]);
                const uint32_t b1 = __float_as_uint(bf[nt * 2 + 1]);
                #pragma unroll
                for (int mt = 0; mt < 4; ++mt)
                    mma_f16(acc[mt][nt], a[mt][0], a[mt][1], a[mt][2], a[mt][3],
                            b0, b1);
            }
        }

        if (g == 1 || g == 9) {
            if (g == 9) __syncthreads();   // layer1 read B1 -> in-place write
            // ReLU + half2 pack, stored k-permuted for the next layer's A reads
            #pragma unroll
            for (int mt = 0; mt < 4; ++mt)
                #pragma unroll
                for (int nt = 0; nt < 8; ++nt) {
                    const int r0 = mb + mt * 16 + grp;
                    const int c0 = nb + nt * 8 + 2 * tig;
                    const int t  = (c0 >> 1) & 7;
                    const int q  = (t < 4) ? 2 * t : 2 * (t - 4) + 1;
                    const int w  = (c0 >> 4) * 8 + q;
                    const uint32_t lo = packh2(fmaxf(acc[mt][nt][0], 0.0f),
                                               fmaxf(acc[mt][nt][1], 0.0f));
                    const uint32_t hi = packh2(fmaxf(acc[mt][nt][2], 0.0f),
                                               fmaxf(acc[mt][nt][3], 0.0f));
                    B1w[r0 * BPW + w]       = lo;
                    B1w[(r0 + 8) * BPW + w] = hi;
                    acc[mt][nt][0] = 0.0f; acc[mt][nt][1] = 0.0f;
                    acc[mt][nt][2] = 0.0f; acc[mt][nt][3] = 0.0f;
                }
        } else if (g == 17) {
            // Fused final: out[r] = sum_c relu(h3[r,c]) * W3[c], from fp32 acc
            #pragma unroll
            for (int mt = 0; mt < 4; ++mt) {
                float s0 = 0.0f, s1 = 0.0f;
                #pragma unroll
                for (int nt = 0; nt < 8; ++nt) {
                    const int c = nb + nt * 8 + 2 * tig;
                    const float wA = W3s[c], wB = W3s[c + 1];
                    s0 = fmaf(fmaxf(acc[mt][nt][0], 0.0f), wA, s0);
                    s0 = fmaf(fmaxf(acc[mt][nt][1], 0.0f), wB, s0);
                    s1 = fmaf(fmaxf(acc[mt][nt][2], 0.0f), wA, s1);
                    s1 = fmaf(fmaxf(acc[mt][nt][3], 0.0f), wB, s1);
                }
                s0 += __shfl_xor_sync(0xffffffffu, s0, 1);
                s0 += __shfl_xor_sync(0xffffffffu, s0, 2);
                s1 += __shfl_xor_sync(0xffffffffu, s1, 1);
                s1 += __shfl_xor_sync(0xffffffffu, s1, 2);
                if (tig == 0) {
                    const int r0 = mb + mt * 16 + grp;
                    part[r0 * 4 + nq]       = s0;
                    part[(r0 + 8) * 4 + nq] = s1;
                }
            }
        }
    }
    __syncthreads();

    if (tid < 128) {
        const float* p4 = part + tid * 4;
        out[blockIdx.x * 128 + tid] = (p4[0] + p4[1]) + (p4[2] + p4[3]);
    }
}

// --------------------------------- launcher ---------------------------------
extern "C" void kernel_launch(void* const* d_in, const int* in_sizes, int n_in,
                              void* d_out, int out_size)
{
    const float* x     = (const float*)d_in[0];
    const float* table = (const float*)d_in[1];
    const float* W0    = (const float*)d_in[2];
    const float* W1    = (const float*)d_in[3];
    const float* W2    = (const float*)d_in[4];
    const float* W3    = (const float*)d_in[5];
    float*       out   = (float*)d_out;

    LevelParams lp;
    for (int l = 0; l < NLEV; ++l) {
        double sc = 16.0 * pow(1.2599210739135742, (double)l) - 1.0;
        int res = (int)ceil(sc) + 1;
        long long sz = (long long)res * (long long)res;
        sz = ((sz + 7) / 8) * 8;
        if (sz > (1LL << 19)) sz = 1LL << 19;
        lp.scale[l] = (float)sc;
        lp.res[l]   = res;
        lp.size[l]  = (int)sz;
    }

    wt_prep<<<288, 256>>>(W0, W1, W2);

    cudaFuncSetAttribute(nf_main, cudaFuncAttributeMaxDynamicSharedMemorySize,
                         SMEM_BYTES);
    nf_main<<<NPTS / 128, THREADS, SMEM_BYTES>>>(x, table, W3, out, lp);
}